// round 7
// baseline (speedup 1.0000x reference)
#include <cuda_runtime.h>

// SE_loss_w_threshold: h,v (8,16384,128) fp32, N scalar.
// out (10 fp32): [mean_Rp, R_per_user[0..7], sum(R_per_user)]
// R7: d-chunked tiles (2 chunks/batch, 4.35KB each) -> 24 warps/SM with a
// depth-2 cp.async pipeline (chunk ch lives in buffer ch). GRID=888.

#define NUSER 8
#define BATCH 16384
#define ROW   68                       // floats per row (64 data + 4 pad)
#define TILEF (NUSER * ROW)            // 544 floats per array per chunk
#define WBUF  (2 * TILEF)              // h+v chunk buffer: 1088 floats
#define WPB   4
#define THREADS (WPB * 32)
#define GRID  888                      // 148 SMs * 6 blocks/SM, single wave
#define VOFF_B (TILEF * 4)             // byte offset of v tile within buffer

typedef unsigned long long u64;

__device__ double gAcc[9];
__device__ unsigned int gCount = 0;

__device__ __forceinline__ u64 ffma2(u64 a, u64 b, u64 c) {
    u64 d;
    asm("fma.rn.f32x2 %0, %1, %2, %3;" : "=l"(d) : "l"(a), "l"(b), "l"(c));
    return d;
}
__device__ __forceinline__ float hsum2(u64 a) {
    float2 f;
    asm("mov.b64 {%0, %1}, %2;" : "=f"(f.x), "=f"(f.y) : "l"(a));
    return f.x + f.y;
}

#define DOT(re, ip, in, hl, hh, vl, vh)            \
    re = ffma2((hl).x, (vl).x, re);                \
    re = ffma2((hl).y, (vl).y, re);                \
    re = ffma2((hh).x, (vh).x, re);                \
    re = ffma2((hh).y, (vh).y, re);                \
    ip = ffma2((hh).x, (vl).x, ip);                \
    ip = ffma2((hh).y, (vl).y, ip);                \
    in = ffma2((hl).x, (vh).x, in);                \
    in = ffma2((hl).y, (vh).y, in);

// stage one (batch, chunk) into the given buffer.
// chunk ch covers global t in [32ch,32ch+32) (lo) and [64+32ch,64+32ch+32) (hi).
__device__ __forceinline__ void prefetch_chunk(const float* __restrict__ hg,
                                               const float* __restrict__ vg,
                                               int b, int ch, int lane,
                                               unsigned bufa)
{
    const int rh  = lane >> 3;         // row-half slot 0..3
    const int blk = lane & 7;          // 16B block within 128B half
    #pragma unroll
    for (int q = 0; q < 4; q++) {
        const int id   = q * 4 + rh;   // 0..15: row-half index
        const int u    = id >> 1;
        const int half = id & 1;
        const size_t g = ((size_t)(u * BATCH + b) << 7)
                       + (size_t)(half * 64 + ch * 32 + blk * 4);
        const unsigned sa = bufa + (unsigned)((u * ROW + half * 32 + blk * 4) * 4);
        asm volatile("cp.async.cg.shared.global [%0], [%1], 16;"
                     :: "r"(sa), "l"(hg + g));
        asm volatile("cp.async.cg.shared.global [%0], [%1], 16;"
                     :: "r"(sa + VOFF_B), "l"(vg + g));
    }
    asm volatile("cp.async.commit_group;");
}

__global__ __launch_bounds__(THREADS, 6)
void se_fused_kernel(const float* __restrict__ hg,
                     const float* __restrict__ vg,
                     const float* __restrict__ Np,
                     float* __restrict__ out, int out_size)
{
    __shared__ __align__(16) float sh[WPB * 2 * WBUF];   // 34816 B
    __shared__ double sAcc[9];
    __shared__ int sLast;

    const int tid  = threadIdx.x;
    const int lane = tid & 31;
    const int wid  = tid >> 5;

    if (tid < 9) sAcc[tid] = 0.0;
    __syncthreads();

    const int gw = blockIdx.x * WPB + wid;
    const int nw = GRID * WPB;

    float* buf0f = sh + (wid * 2) * WBUF;
    float* buf1f = buf0f + WBUF;
    const unsigned buf0a = (unsigned)__cvta_generic_to_shared(buf0f);
    const unsigned buf1a = buf0a + WBUF * 4;

    const float Nval = __ldg(Np);

    // lane decomposition: c = col pair, a = row pair, k2 = t-split
    const int c  = lane & 3;
    const int a  = (lane >> 2) & 3;
    const int k2 = lane >> 4;
    const int t0 = k2 * 4;

    // nrm readback addressing (same pieces this lane staged)
    const int rh  = lane >> 3;
    const int blk = lane & 7;

    float accRp = 0.0f, accR0 = 0.0f, accR1 = 0.0f;

    // pipeline fill: both chunks of the first batch
    prefetch_chunk(hg, vg, gw, 0, lane, buf0a);
    prefetch_chunk(hg, vg, gw, 1, lane, buf1a);

    for (int b = gw; b < BATCH; b += nw) {
        const int bn = b + nw;

        u64 nrm2 = 0ULL;
        u64 re00 = 0, ip00 = 0, in00 = 0;
        u64 re01 = 0, ip01 = 0, in01 = 0;
        u64 re10 = 0, ip10 = 0, in10 = 0;
        u64 re11 = 0, ip11 = 0, in11 = 0;

        #pragma unroll
        for (int ch = 0; ch < 2; ch++) {
            asm volatile("cp.async.wait_group 1;" ::: "memory");
            __syncwarp();

            float* wb = ch ? buf1f : buf0f;
            const float* hr0 = wb + (2 * a) * ROW;
            const float* hr1 = hr0 + ROW;
            const float* vc0 = wb + TILEF + (2 * c) * ROW;
            const float* vc1 = vc0 + ROW;

            // ||v||^2 partial: read back this lane's staged v pieces
            #pragma unroll
            for (int q = 0; q < 4; q++) {
                const int id   = q * 4 + rh;
                const int u    = id >> 1;
                const int half = id & 1;
                const ulonglong2 vv = *(const ulonglong2*)
                    (wb + TILEF + u * ROW + half * 32 + blk * 4);
                nrm2 = ffma2(vv.x, vv.x, nrm2);
                nrm2 = ffma2(vv.y, vv.y, nrm2);
            }

            // 2x2 complex-dot block over this lane's quarter of t
            #pragma unroll
            for (int m = 0; m < 4; m++) {
                const int off = t0 + m * 8;
                const ulonglong2 h0l = *(const ulonglong2*)(hr0 + off);
                const ulonglong2 h0h = *(const ulonglong2*)(hr0 + off + 32);
                const ulonglong2 h1l = *(const ulonglong2*)(hr1 + off);
                const ulonglong2 h1h = *(const ulonglong2*)(hr1 + off + 32);
                const ulonglong2 v0l = *(const ulonglong2*)(vc0 + off);
                const ulonglong2 v0h = *(const ulonglong2*)(vc0 + off + 32);
                const ulonglong2 v1l = *(const ulonglong2*)(vc1 + off);
                const ulonglong2 v1h = *(const ulonglong2*)(vc1 + off + 32);

                DOT(re00, ip00, in00, h0l, h0h, v0l, v0h)
                DOT(re01, ip01, in01, h0l, h0h, v1l, v1h)
                DOT(re10, ip10, in10, h1l, h1h, v0l, v0h)
                DOT(re11, ip11, in11, h1l, h1h, v1l, v1h)
            }

            __syncwarp();   // buffer fully consumed -> safe to refill
            if (bn < BATCH) {
                prefetch_chunk(hg, vg, bn, ch, lane, ch ? buf1a : buf0a);
            } else {
                asm volatile("cp.async.commit_group;");   // keep group count
            }
        }

        // ---- per-batch reductions (registers/shuffles only) ----
        float nrm = hsum2(nrm2);
        #pragma unroll
        for (int o = 16; o; o >>= 1)
            nrm += __shfl_xor_sync(0xffffffffu, nrm, o);

        float Ar00 = hsum2(re00), Ai00 = hsum2(ip00) - hsum2(in00);
        float Ar01 = hsum2(re01), Ai01 = hsum2(ip01) - hsum2(in01);
        float Ar10 = hsum2(re10), Ai10 = hsum2(ip10) - hsum2(in10);
        float Ar11 = hsum2(re11), Ai11 = hsum2(ip11) - hsum2(in11);

        Ar00 += __shfl_xor_sync(0xffffffffu, Ar00, 16);
        Ai00 += __shfl_xor_sync(0xffffffffu, Ai00, 16);
        Ar01 += __shfl_xor_sync(0xffffffffu, Ar01, 16);
        Ai01 += __shfl_xor_sync(0xffffffffu, Ai01, 16);
        Ar10 += __shfl_xor_sync(0xffffffffu, Ar10, 16);
        Ai10 += __shfl_xor_sync(0xffffffffu, Ai10, 16);
        Ar11 += __shfl_xor_sync(0xffffffffu, Ar11, 16);
        Ai11 += __shfl_xor_sync(0xffffffffu, Ai11, 16);

        const float p00 = fmaf(Ar00, Ar00, Ai00 * Ai00);
        const float p01 = fmaf(Ar01, Ar01, Ai01 * Ai01);
        const float p10 = fmaf(Ar10, Ar10, Ai10 * Ai10);
        const float p11 = fmaf(Ar11, Ar11, Ai11 * Ai11);

        const float d0 = p00, d1 = p11;     // valid on lanes c==a

        float s0 = p00 + p01;
        float s1 = p10 + p11;
        s0 += __shfl_xor_sync(0xffffffffu, s0, 1);
        s1 += __shfl_xor_sync(0xffffffffu, s1, 1);
        s0 += __shfl_xor_sync(0xffffffffu, s0, 2);
        s1 += __shfl_xor_sync(0xffffffffu, s1, 2);

        if (c == a && k2 == 0) {
            const float scale2 = 8.0f / nrm;
            const float sinr0 = __fdividef(d0 * scale2, s0 - d0 + Nval);
            const float sinr1 = __fdividef(d1 * scale2, s1 - d1 + Nval);
            const float R0 = __log2f(1.0f + sinr0);
            const float R1 = __log2f(1.0f + sinr1);
            accR0 += R0;
            accR1 += R1;
            accRp += __exp10f(0.3f - R0) - R0
                   + __exp10f(0.3f - R1) - R1;
        }
    }

    // ---- block-level reduction ----
    if (c == a && k2 == 0) {
        atomicAdd(&sAcc[0],         (double)accRp);
        atomicAdd(&sAcc[1 + 2 * a], (double)accR0);
        atomicAdd(&sAcc[2 + 2 * a], (double)accR1);
    }
    __syncthreads();

    if (tid < 9) atomicAdd(&gAcc[tid], sAcc[tid]);
    __threadfence();
    __syncthreads();

    if (tid == 0) {
        const unsigned old = atomicInc(&gCount, GRID - 1);
        sLast = (old == GRID - 1) ? 1 : 0;
    }
    __syncthreads();

    if (sLast && tid == 0) {
        __threadfence();
        const double inv = 1.0 / (double)BATCH;
        double r[9];
        #pragma unroll
        for (int i = 0; i < 9; i++) {
            r[i] = __ldcg(&gAcc[i]);
            __stcg(&gAcc[i], 0.0);
        }
        double s = 0.0;
        #pragma unroll
        for (int i = 1; i < 9; i++) s += r[i] * inv;
        if (out_size >= 1) out[0] = (float)(r[0] * inv);
        if (out_size >= 10) {
            #pragma unroll
            for (int i = 0; i < 8; i++) out[1 + i] = (float)(r[1 + i] * inv);
            out[9] = (float)s;
        }
    }
}

extern "C" void kernel_launch(void* const* d_in, const int* in_sizes, int n_in,
                              void* d_out, int out_size)
{
    const float* h = (const float*)d_in[0];
    const float* v = (const float*)d_in[1];
    const float* N = (const float*)d_in[2];
    float* out = (float*)d_out;

    se_fused_kernel<<<GRID, THREADS>>>(h, v, N, out, out_size);
}